// round 2
// baseline (speedup 1.0000x reference)
#include <cuda_runtime.h>

// ReNet layer: vertical bidirectional LSTM sweep over 2x2x3 patches, then
// horizontal bidirectional LSTM sweep. Exact fp32 math (fma.rn.f32x2 packed).
//
// Phase kernel: each CTA owns 32 sequences of one direction. Combined weight
// matrix [K][256] (K = DIN+64) lives in smem; per-seq vector xh[K] (input ++ h)
// lives in smem; c-state in registers. 128 threads: 4 seq-groups x 32 col-groups,
// per-thread tile = 8 seqs x (2 hid x 4 gates), FFMA2-packed over the hid pair.

#define HIDN 64
#define NGC  256      // 4*HID gate columns
#define BN   16
#define SJ   128      // J == I == 128 patches
#define NSEQ 32       // sequences per CTA
#define NTHR 128

typedef unsigned long long ull;

__device__ float g_v[BN * SJ * SJ * 2 * HIDN];   // vertical output [B][J][I][128], 134 MB

__device__ __forceinline__ ull pack2(float lo, float hi) {
    ull r; asm("mov.b64 %0, {%1, %2};" : "=l"(r) : "f"(lo), "f"(hi)); return r;
}
__device__ __forceinline__ void unpack2(ull v, float& lo, float& hi) {
    asm("mov.b64 {%0, %1}, %2;" : "=f"(lo), "=f"(hi) : "l"(v));
}
__device__ __forceinline__ void ffma2(ull& d, ull a, ull b) {
    asm("fma.rn.f32x2 %0, %1, %2, %0;" : "+l"(d) : "l"(a), "l"(b));
}
__device__ __forceinline__ float sigf(float x)   { return 1.0f / (1.0f + __expf(-x)); }
__device__ __forceinline__ float mytanh(float x) { return 1.0f - 2.0f / (__expf(2.0f * x) + 1.0f); }

template <int DIN>
__global__ void __launch_bounds__(NTHR, 1)
renet_pass(const float* __restrict__ W0, const float* __restrict__ U0, const float* __restrict__ b0,
           const float* __restrict__ W1, const float* __restrict__ U1, const float* __restrict__ b1,
           const float* __restrict__ src, float* __restrict__ dst)
{
    constexpr int K = DIN + HIDN;
    extern __shared__ float sm[];
    float* sWU = sm;                   // [K][NGC]   combined W;U
    float* sXH = sm + K * NGC;         // [NSEQ][K]  per-seq (x_t ++ h)
    float* sB  = sXH + NSEQ * K;       // [NGC]

    const int dir = blockIdx.x >> 6;          // 0: forward scan, 1: reversed input
    const int s0  = (blockIdx.x & 63) * NSEQ; // first sequence of this CTA
    const int tid = threadIdx.x;
    const int cg  = tid & 31;                 // column group: hid pair h0 = 2*cg
    const int sg  = tid >> 5;                 // seq group (warp): 8 seqs each
    const int h0  = 2 * cg;

    const float* W  = dir ? W1 : W0;
    const float* U  = dir ? U1 : U0;
    const float* bb = dir ? b1 : b0;

    for (int idx = tid; idx < DIN * NGC; idx += NTHR) sWU[idx] = W[idx];
    for (int idx = tid; idx < HIDN * NGC; idx += NTHR) sWU[DIN * NGC + idx] = U[idx];
    for (int idx = tid; idx < NGC; idx += NTHR) sB[idx] = bb[idx];
    for (int idx = tid; idx < NSEQ * HIDN; idx += NTHR) {
        int s = idx >> 6, h = idx & 63;
        sXH[s * K + DIN + h] = 0.0f;           // h_0 = 0
    }
    __syncthreads();

    ull biasr[4];
#pragma unroll
    for (int g = 0; g < 4; g++) biasr[g] = *(const ull*)&sB[g * HIDN + h0];

    float cst[16];                             // c-state: 8 seqs x 2 hid
#pragma unroll
    for (int p = 0; p < 16; p++) cst[p] = 0.0f;

    for (int t = 0; t < SJ; t++) {
        // ---- stage x_t into sXH[s][0..DIN)
        if (DIN == 12) {
            const int jin = dir ? (SJ - 1 - t) : t;
#pragma unroll
            for (int r = 0; r < 3; r++) {
                int e = tid + NTHR * r;        // 384 = 32 seq * 12
                int s = e / 12, d = e - s * 12;
                int q = s0 + s;
                int b = q >> 7, i = q & 127;
                int pr = d / 6, rm = d - pr * 6;
                int pc = rm / 3, ch = rm - pc * 3;
                sXH[s * K + d] =
                    src[((b * 256 + (2 * jin + pr)) * 256 + (2 * i + pc)) * 3 + ch];
            }
        } else {
            const int iin = dir ? (SJ - 1 - t) : t;
#pragma unroll
            for (int r = 0; r < 8; r++) {
                int idx = tid + NTHR * r;      // 1024 = 32 seq * 32 float4
                int s = idx >> 5, f4 = idx & 31;
                int q = s0 + s;
                int b = q >> 7, j = q & 127;
                float4 v4 = *(const float4*)
                    &src[((size_t)((b * 128 + j) * 128 + iin)) * 128 + f4 * 4];
                *(float4*)&sXH[s * K + f4 * 4] = v4;
            }
        }
        __syncthreads();   // x_t staged; h from step t-1 visible

        // ---- Z[s][c] = bias + (x ++ h) @ (W ;; U)
        ull acc[8][4];
#pragma unroll
        for (int m = 0; m < 8; m++)
#pragma unroll
            for (int g = 0; g < 4; g++) acc[m][g] = biasr[g];

        const float* xbase = sXH + (sg * 8) * K;
#pragma unroll 2
        for (int k = 0; k < K; k++) {
            const float* wr = sWU + k * NGC + h0;
            ull u0 = *(const ull*)(wr);
            ull u1 = *(const ull*)(wr + 64);
            ull u2 = *(const ull*)(wr + 128);
            ull u3 = *(const ull*)(wr + 192);
#pragma unroll
            for (int m = 0; m < 8; m++) {
                float a = xbase[m * K + k];    // broadcast within warp
                ull a2 = pack2(a, a);
                ffma2(acc[m][0], a2, u0);
                ffma2(acc[m][1], a2, u1);
                ffma2(acc[m][2], a2, u2);
                ffma2(acc[m][3], a2, u3);
            }
        }
        __syncthreads();   // everyone done reading sXH before h overwrite

        // ---- gates, state update, h write-back + global store
#pragma unroll
        for (int m = 0; m < 8; m++) {
            float zi0, zi1, zf0, zf1, zg0, zg1, zo0, zo1;
            unpack2(acc[m][0], zi0, zi1);
            unpack2(acc[m][1], zf0, zf1);
            unpack2(acc[m][2], zg0, zg1);
            unpack2(acc[m][3], zo0, zo1);
            float c0 = cst[2 * m], c1 = cst[2 * m + 1];
            c0 = sigf(zf0) * c0 + sigf(zi0) * mytanh(zg0);
            c1 = sigf(zf1) * c1 + sigf(zi1) * mytanh(zg1);
            cst[2 * m] = c0; cst[2 * m + 1] = c1;
            float hh0 = sigf(zo0) * mytanh(c0);
            float hh1 = sigf(zo1) * mytanh(c1);

            int s = sg * 8 + m;
            *(float2*)&sXH[s * K + DIN + h0] = make_float2(hh0, hh1);

            int q = s0 + s;
            int b = q >> 7, w = q & 127;
            // vertical:   v[b][t][w][dir*64 + h]   (seq index w = column i)
            // horizontal: out[b][w][t][dir*64 + h] (seq index w = row j)
            int row = (DIN == 12) ? t : w;
            int col = (DIN == 12) ? w : t;
            size_t off = ((size_t)((b * 128 + row) * 128 + col)) * 128 + dir * 64 + h0;
            *(float2*)&dst[off] = make_float2(hh0, hh1);
        }
        // note: no sync needed here; next-iter x staging writes a disjoint smem
        // region, and the next __syncthreads() orders h writes vs. GEMM reads.
    }
}

extern "C" void kernel_launch(void* const* d_in, const int* in_sizes, int n_in,
                              void* d_out, int out_size)
{
    const float* inputs = (const float*)d_in[0];
    const float* W_ud = (const float*)d_in[1];
    const float* U_ud = (const float*)d_in[2];
    const float* b_ud = (const float*)d_in[3];
    const float* W_du = (const float*)d_in[4];
    const float* U_du = (const float*)d_in[5];
    const float* b_du = (const float*)d_in[6];
    const float* W_lr = (const float*)d_in[7];
    const float* U_lr = (const float*)d_in[8];
    const float* b_lr = (const float*)d_in[9];
    const float* W_rl = (const float*)d_in[10];
    const float* U_rl = (const float*)d_in[11];
    const float* b_rl = (const float*)d_in[12];

    float* vbuf = nullptr;
    cudaGetSymbolAddress((void**)&vbuf, g_v);

    constexpr int K1 = 12 + HIDN;    // 76
    constexpr int K2 = 128 + HIDN;   // 192
    size_t smem1 = (size_t)(K1 * NGC + NSEQ * K1 + NGC) * sizeof(float);  //  88,576 B
    size_t smem2 = (size_t)(K2 * NGC + NSEQ * K2 + NGC) * sizeof(float);  // 222,208 B

    cudaFuncSetAttribute(renet_pass<12>,  cudaFuncAttributeMaxDynamicSharedMemorySize, (int)smem1);
    cudaFuncSetAttribute(renet_pass<128>, cudaFuncAttributeMaxDynamicSharedMemorySize, (int)smem2);

    // vertical sweep: 2 dirs x 2048 seqs (seq = b*128 + i), writes g_v[B][J][I][128]
    renet_pass<12><<<128, NTHR, smem1>>>(W_ud, U_ud, b_ud, W_du, U_du, b_du,
                                         inputs, vbuf);
    // horizontal sweep: 2 dirs x 2048 seqs (seq = b*128 + j), writes out[B][J][I][128]
    renet_pass<128><<<128, NTHR, smem2>>>(W_lr, U_lr, b_lr, W_rl, U_rl, b_rl,
                                          vbuf, (float*)d_out);
}

// round 3
// speedup vs baseline: 1.0777x; 1.0777x over previous
#include <cuda_runtime.h>

// ReNet layer: vertical bidirectional LSTM sweep over 2x2x3 patches, then
// horizontal bidirectional LSTM sweep. Exact fp32 math (fma.rn.f32x2 packed).
//
// R2: K-split warp pairs. 256 threads = 4 seq-groups x 2 K-halves. Each warp
// computes partial Z over half the K range for 8 seqs x 256 gate-cols, giving
// 2 warps/SMSP (latency hiding) WITHOUT doubling smem weight traffic. Partials
// combined through a two-round (gate-pair) smem exchange; for the horizontal
// pass the exchange buffer aliases the x staging region of sXH.

#define HIDN 64
#define NGC  256      // 4*HID gate columns
#define BN   16
#define SJ   128      // J == I == 128 patches
#define NSEQ 32       // sequences per CTA
#define NTHR 256

typedef unsigned long long ull;

__device__ float g_v[BN * SJ * SJ * 2 * HIDN];   // vertical output [B][J][I][128]

__device__ __forceinline__ ull pack2(float lo, float hi) {
    ull r; asm("mov.b64 %0, {%1, %2};" : "=l"(r) : "f"(lo), "f"(hi)); return r;
}
__device__ __forceinline__ void unpack2(ull v, float& lo, float& hi) {
    asm("mov.b64 {%0, %1}, %2;" : "=f"(lo), "=f"(hi) : "l"(v));
}
__device__ __forceinline__ void ffma2(ull& d, ull a, ull b) {
    asm("fma.rn.f32x2 %0, %1, %2, %0;" : "+l"(d) : "l"(a), "l"(b));
}
__device__ __forceinline__ ull addf2(ull a, ull b) {
    ull r; asm("add.rn.f32x2 %0, %1, %2;" : "=l"(r) : "l"(a), "l"(b)); return r;
}
__device__ __forceinline__ float sigf(float x)   { return 1.0f / (1.0f + __expf(-x)); }
__device__ __forceinline__ float mytanh(float x) { return 1.0f - 2.0f / (__expf(2.0f * x) + 1.0f); }

template <int DIN>
__global__ void __launch_bounds__(NTHR, 1)
renet_pass(const float* __restrict__ W0, const float* __restrict__ U0, const float* __restrict__ b0,
           const float* __restrict__ W1, const float* __restrict__ U1, const float* __restrict__ b1,
           const float* __restrict__ src, float* __restrict__ dst)
{
    constexpr int K  = DIN + HIDN;
    constexpr int KA = ((K / 2) + 3) & ~3;        // kh=0 handles [0,KA), kh=1 [KA,K); both %4==0
    extern __shared__ float sm[];
    float* sWU = sm;                   // [K][NGC]   combined W;U, column-permuted
    float* sXH = sm + K * NGC;         // [NSEQ][K]  per-seq (x_t ++ h)
    float* sB  = sXH + NSEQ * K;       // [NGC]
    float* sP  = sB + NGC;             // [NSEQ][128] partial buffer (vertical only)

    const int dir  = blockIdx.x >> 6;
    const int s0   = (blockIdx.x & 63) * NSEQ;
    const int tid  = threadIdx.x;
    const int lane = tid & 31;
    const int wid  = tid >> 5;
    const int kh   = wid & 1;                 // K-half
    const int sg   = wid >> 1;                // seq group: 8 seqs
    const int h0   = 2 * lane;

    const float* W  = dir ? W1 : W0;
    const float* U  = dir ? U1 : U0;
    const float* bb = dir ? b1 : b0;

    // load weights permuted: sWU[k][ lane*8 + g*2 + (h&1) ] = orig[k][g*64 + h], h=2*lane+(h&1)
    for (int idx = tid; idx < K * NGC; idx += NTHR) {
        int k = idx >> 8, c = idx & 255;
        int g = c >> 6, h = c & 63;
        int pc = (h >> 1) * 8 + g * 2 + (h & 1);
        float v = (k < DIN) ? W[k * NGC + c] : U[(k - DIN) * NGC + c];
        sWU[k * NGC + pc] = v;
    }
    for (int idx = tid; idx < NGC; idx += NTHR) sB[idx] = bb[idx];
    for (int idx = tid; idx < NSEQ * HIDN; idx += NTHR) {
        int s = idx >> 6, h = idx & 63;
        sXH[s * K + DIN + h] = 0.0f;           // h_0 = 0
    }
    __syncthreads();

    ull binit[4];
#pragma unroll
    for (int g = 0; g < 4; g++)
        binit[g] = kh ? 0ull : *(const ull*)&sB[g * HIDN + h0];

    float cst[16];
#pragma unroll
    for (int p = 0; p < 16; p++) cst[p] = 0.0f;

    const int kbeg = kh ? KA : 0;
    const int kend = kh ? K : KA;
    // partial-exchange row for seq s (horizontal: aliases x part of sXH row)
    float* prbase   = (DIN == 12) ? sP : sXH;
    const int prstr = (DIN == 12) ? 128 : K;

    for (int t = 0; t < SJ; t++) {
        // ---- stage x_t into sXH[s][0..DIN)
        if (DIN == 12) {
            const int jin = dir ? (SJ - 1 - t) : t;
            for (int e = tid; e < NSEQ * 12; e += NTHR) {
                int s = e / 12, d = e - s * 12;
                int q = s0 + s;
                int b = q >> 7, i = q & 127;
                int pr = d / 6, rm = d - pr * 6;
                int pc = rm / 3, ch = rm - pc * 3;
                sXH[s * K + d] =
                    src[((b * 256 + (2 * jin + pr)) * 256 + (2 * i + pc)) * 3 + ch];
            }
        } else {
            const int iin = dir ? (SJ - 1 - t) : t;
#pragma unroll
            for (int r = 0; r < 4; r++) {
                int idx = tid + NTHR * r;      // 1024 = 32 seq * 32 float4
                int s = idx >> 5, f4 = idx & 31;
                int q = s0 + s;
                int b = q >> 7, j = q & 127;
                float4 v4 = *(const float4*)
                    &src[((size_t)((b * 128 + j) * 128 + iin)) * 128 + f4 * 4];
                *(float4*)&sXH[s * K + f4 * 4] = v4;
            }
        }
        __syncthreads();                                   // A: x staged, h visible

        // ---- partial Z over this warp's K half
        ull acc[8][4];
#pragma unroll
        for (int m = 0; m < 8; m++)
#pragma unroll
            for (int g = 0; g < 4; g++) acc[m][g] = binit[g];

        const float* xbase = sXH + (sg * 8) * K;
        for (int k = kbeg; k < kend; k += 4) {
            float4 xq[8];
#pragma unroll
            for (int m = 0; m < 8; m++)
                xq[m] = *(const float4*)&xbase[m * K + k];
            const float* xf = (const float*)xq;
#pragma unroll
            for (int kk = 0; kk < 4; kk++) {
                const float* wr = sWU + (k + kk) * NGC + lane * 8;
                ulonglong2 wA = *(const ulonglong2*)(wr);      // gates i,f
                ulonglong2 wB = *(const ulonglong2*)(wr + 4);  // gates g,o
#pragma unroll
                for (int m = 0; m < 8; m++) {
                    float a = xf[m * 4 + kk];
                    ull a2 = pack2(a, a);
                    ffma2(acc[m][0], a2, wA.x);
                    ffma2(acc[m][1], a2, wA.y);
                    ffma2(acc[m][2], a2, wB.x);
                    ffma2(acc[m][3], a2, wB.y);
                }
            }
        }
        __syncthreads();                                   // B: GEMM done (x region free)

        // ---- round A: exchange gate-pair (i,f)
        if (kh == 1) {
#pragma unroll
            for (int m = 0; m < 8; m++) {
                float* pr = prbase + (sg * 8 + m) * prstr;
                *(ull*)(pr + h0)      = acc[m][0];
                *(ull*)(pr + 64 + h0) = acc[m][1];
            }
        }
        __syncthreads();                                   // C
        if (kh == 0) {
#pragma unroll
            for (int m = 0; m < 8; m++) {
                const float* pr = prbase + (sg * 8 + m) * prstr;
                acc[m][0] = addf2(acc[m][0], *(const ull*)(pr + h0));
                acc[m][1] = addf2(acc[m][1], *(const ull*)(pr + 64 + h0));
            }
        }
        __syncthreads();                                   // D
        // ---- round B: exchange gate-pair (g,o)
        if (kh == 1) {
#pragma unroll
            for (int m = 0; m < 8; m++) {
                float* pr = prbase + (sg * 8 + m) * prstr;
                *(ull*)(pr + h0)      = acc[m][2];
                *(ull*)(pr + 64 + h0) = acc[m][3];
            }
        }
        __syncthreads();                                   // E

        // ---- gates, state update, h + output (kh==0 warps only)
        if (kh == 0) {
#pragma unroll
            for (int m = 0; m < 8; m++) {
                const float* pr = prbase + (sg * 8 + m) * prstr;
                ull zg2 = addf2(acc[m][2], *(const ull*)(pr + h0));
                ull zo2 = addf2(acc[m][3], *(const ull*)(pr + 64 + h0));
                float zi0, zi1, zf0, zf1, zg0, zg1, zo0, zo1;
                unpack2(acc[m][0], zi0, zi1);
                unpack2(acc[m][1], zf0, zf1);
                unpack2(zg2, zg0, zg1);
                unpack2(zo2, zo0, zo1);
                float c0 = cst[2 * m], c1 = cst[2 * m + 1];
                c0 = sigf(zf0) * c0 + sigf(zi0) * mytanh(zg0);
                c1 = sigf(zf1) * c1 + sigf(zi1) * mytanh(zg1);
                cst[2 * m] = c0; cst[2 * m + 1] = c1;
                float hh0 = sigf(zo0) * mytanh(c0);
                float hh1 = sigf(zo1) * mytanh(c1);

                int s = sg * 8 + m;
                *(float2*)&sXH[s * K + DIN + h0] = make_float2(hh0, hh1);

                int q = s0 + s;
                int b = q >> 7, w = q & 127;
                int row = (DIN == 12) ? t : w;
                int col = (DIN == 12) ? w : t;
                size_t off = ((size_t)((b * 128 + row) * 128 + col)) * 128 + dir * 64 + h0;
                *(float2*)&dst[off] = make_float2(hh0, hh1);
            }
        }
        __syncthreads();                                   // F: h ready, pbuf free
    }
}

extern "C" void kernel_launch(void* const* d_in, const int* in_sizes, int n_in,
                              void* d_out, int out_size)
{
    const float* inputs = (const float*)d_in[0];
    const float* W_ud = (const float*)d_in[1];
    const float* U_ud = (const float*)d_in[2];
    const float* b_ud = (const float*)d_in[3];
    const float* W_du = (const float*)d_in[4];
    const float* U_du = (const float*)d_in[5];
    const float* b_du = (const float*)d_in[6];
    const float* W_lr = (const float*)d_in[7];
    const float* U_lr = (const float*)d_in[8];
    const float* b_lr = (const float*)d_in[9];
    const float* W_rl = (const float*)d_in[10];
    const float* U_rl = (const float*)d_in[11];
    const float* b_rl = (const float*)d_in[12];

    float* vbuf = nullptr;
    cudaGetSymbolAddress((void**)&vbuf, g_v);

    constexpr int K1 = 12 + HIDN;    // 76
    constexpr int K2 = 128 + HIDN;   // 192
    // vertical needs a dedicated 16KB partial buffer; horizontal aliases sXH x-region
    size_t smem1 = (size_t)(K1 * NGC + NSEQ * K1 + NGC + NSEQ * 128) * sizeof(float); // 104,960
    size_t smem2 = (size_t)(K2 * NGC + NSEQ * K2 + NGC) * sizeof(float);              // 222,208

    cudaFuncSetAttribute(renet_pass<12>,  cudaFuncAttributeMaxDynamicSharedMemorySize, (int)smem1);
    cudaFuncSetAttribute(renet_pass<128>, cudaFuncAttributeMaxDynamicSharedMemorySize, (int)smem2);

    renet_pass<12><<<128, NTHR, smem1>>>(W_ud, U_ud, b_ud, W_du, U_du, b_du,
                                         inputs, vbuf);
    renet_pass<128><<<128, NTHR, smem2>>>(W_lr, U_lr, b_lr, W_rl, U_rl, b_rl,
                                          vbuf, (float*)d_out);
}

// round 4
// speedup vs baseline: 1.3983x; 1.2974x over previous
#include <cuda_runtime.h>

// ReNet layer: vertical bidirectional LSTM sweep over 2x2x3 patches, then
// horizontal bidirectional LSTM sweep. Exact fp32 math (fma.rn.f32x2 packed).
//
// R3: hid-half split, no reduction. 256 threads = 4 seq-groups x 2 hid-halves.
// Each warp: full K, 8 seqs x 32 hid (1 hid/lane), gates packed (i,f),(g,o)
// so every warp owns complete gate sets -> no cross-warp partial exchange,
// 2 syncs/step. Weights stored [k][hh*128 + lane*4 + gate] -> conflict-free
// LDS.128.

#define HIDN 64
#define NGC  256      // 4*HID gate columns
#define BN   16
#define SJ   128      // J == I == 128 patches
#define NSEQ 32       // sequences per CTA
#define NTHR 256

typedef unsigned long long ull;

__device__ float g_v[BN * SJ * SJ * 2 * HIDN];   // vertical output [B][J][I][128]

__device__ __forceinline__ ull pack2(float lo, float hi) {
    ull r; asm("mov.b64 %0, {%1, %2};" : "=l"(r) : "f"(lo), "f"(hi)); return r;
}
__device__ __forceinline__ void unpack2(ull v, float& lo, float& hi) {
    asm("mov.b64 {%0, %1}, %2;" : "=f"(lo), "=f"(hi) : "l"(v));
}
__device__ __forceinline__ void ffma2(ull& d, ull a, ull b) {
    asm("fma.rn.f32x2 %0, %1, %2, %0;" : "+l"(d) : "l"(a), "l"(b));
}
__device__ __forceinline__ float sigf(float x)   { return 1.0f / (1.0f + __expf(-x)); }
__device__ __forceinline__ float mytanh(float x) { return 1.0f - 2.0f / (__expf(2.0f * x) + 1.0f); }

template <int DIN>
__global__ void __launch_bounds__(NTHR, 1)
renet_pass(const float* __restrict__ W0, const float* __restrict__ U0, const float* __restrict__ b0,
           const float* __restrict__ W1, const float* __restrict__ U1, const float* __restrict__ b1,
           const float* __restrict__ src, float* __restrict__ dst)
{
    constexpr int K = DIN + HIDN;
    extern __shared__ float sm[];
    float* sWU = sm;                   // [K][NGC]  combined W;U, gate-pair layout
    float* sXH = sm + K * NGC;         // [NSEQ][K] per-seq (x_t ++ h)
    float* sB  = sXH + NSEQ * K;       // [NGC]

    const int dir  = blockIdx.x >> 6;
    const int s0   = (blockIdx.x & 63) * NSEQ;
    const int tid  = threadIdx.x;
    const int lane = tid & 31;
    const int wid  = tid >> 5;
    const int hh   = wid & 1;                 // hid half
    const int sg   = wid >> 1;                // seq group: 8 seqs
    const int hid  = hh * 32 + lane;          // this lane's hidden index

    const float* W  = dir ? W1 : W0;
    const float* U  = dir ? U1 : U0;
    const float* bb = dir ? b1 : b0;

    // weight layout: sWU[k][ (h>>5)*128 + (h&31)*4 + g ] = orig[k][g*64 + h]
    // -> per (warp,k): LDS.128 at lane*16B, conflict-free; float4 = (wi,wf,wg,wo)
    for (int idx = tid; idx < K * NGC; idx += NTHR) {
        int k = idx >> 8, c = idx & 255;
        int g = c >> 6, h = c & 63;
        int pc = (h >> 5) * 128 + (h & 31) * 4 + g;
        float v = (k < DIN) ? W[k * NGC + c] : U[(k - DIN) * NGC + c];
        sWU[k * NGC + pc] = v;
    }
    for (int idx = tid; idx < NGC; idx += NTHR) sB[idx] = bb[idx];
    for (int idx = tid; idx < NSEQ * HIDN; idx += NTHR) {
        int s = idx >> 6, h = idx & 63;
        sXH[s * K + DIN + h] = 0.0f;           // h_0 = 0
    }
    __syncthreads();

    // bias packed per lane: (b_i,b_f) and (b_g,b_o) for this hid
    ull binit[2];
    binit[0] = pack2(sB[0 * HIDN + hid], sB[1 * HIDN + hid]);
    binit[1] = pack2(sB[2 * HIDN + hid], sB[3 * HIDN + hid]);

    float cst[8];                              // c-state: 8 seqs x 1 hid
#pragma unroll
    for (int p = 0; p < 8; p++) cst[p] = 0.0f;

    // ---- stage x_0
    {
        if (DIN == 12) {
            const int jin = dir ? (SJ - 1) : 0;
            for (int e = tid; e < NSEQ * 12; e += NTHR) {
                int s = e / 12, d = e - s * 12;
                int q = s0 + s;
                int b = q >> 7, i = q & 127;
                int pr = d / 6, rm = d - pr * 6;
                int pc = rm / 3, ch = rm - pc * 3;
                sXH[s * K + d] =
                    src[((b * 256 + (2 * jin + pr)) * 256 + (2 * i + pc)) * 3 + ch];
            }
        } else {
            const int iin = dir ? (SJ - 1) : 0;
#pragma unroll
            for (int r = 0; r < 4; r++) {
                int idx = tid + NTHR * r;
                int s = idx >> 5, f4 = idx & 31;
                int q = s0 + s;
                int b = q >> 7, j = q & 127;
                float4 v4 = *(const float4*)
                    &src[((size_t)((b * 128 + j) * 128 + iin)) * 128 + f4 * 4];
                *(float4*)&sXH[s * K + f4 * 4] = v4;
            }
        }
    }

    for (int t = 0; t < SJ; t++) {
        __syncthreads();                       // A: x_t staged, h_{t-1} visible

        // ---- Z[s][hid gates] = bias + (x ++ h) @ (W ;; U), full K per warp
        ull acc[8][2];
#pragma unroll
        for (int m = 0; m < 8; m++) {
            acc[m][0] = binit[0];
            acc[m][1] = binit[1];
        }

        const float* xbase = sXH + (sg * 8) * K;
        const float* wbase = sWU + hh * 128 + lane * 4;
#pragma unroll 2
        for (int k = 0; k < K; k += 4) {
            float4 xq[8];
#pragma unroll
            for (int m = 0; m < 8; m++)
                xq[m] = *(const float4*)&xbase[m * K + k];
            const float* xf = (const float*)xq;
#pragma unroll
            for (int kk = 0; kk < 4; kk++) {
                ulonglong2 w2 = *(const ulonglong2*)(wbase + (k + kk) * NGC);
#pragma unroll
                for (int m = 0; m < 8; m++) {
                    float a = xf[m * 4 + kk];
                    ull a2 = pack2(a, a);
                    ffma2(acc[m][0], a2, w2.x);   // (zi, zf)
                    ffma2(acc[m][1], a2, w2.y);   // (zg, zo)
                }
            }
        }
        __syncthreads();                       // B: all sXH reads done

        // ---- gates, state update, h write-back + global store
#pragma unroll
        for (int m = 0; m < 8; m++) {
            float zi, zf, zg, zo;
            unpack2(acc[m][0], zi, zf);
            unpack2(acc[m][1], zg, zo);
            float c = sigf(zf) * cst[m] + sigf(zi) * mytanh(zg);
            cst[m] = c;
            float hv = sigf(zo) * mytanh(c);

            int s = sg * 8 + m;
            sXH[s * K + DIN + hid] = hv;

            int q = s0 + s;
            int b = q >> 7, w = q & 127;
            int row = (DIN == 12) ? t : w;
            int col = (DIN == 12) ? w : t;
            dst[((size_t)((b * 128 + row) * 128 + col)) * 128 + dir * 64 + hid] = hv;
        }

        // ---- stage x_{t+1} (disjoint smem region; reads of x_t finished)
        if (t + 1 < SJ) {
            if (DIN == 12) {
                const int jin = dir ? (SJ - 2 - t) : (t + 1);
                for (int e = tid; e < NSEQ * 12; e += NTHR) {
                    int s = e / 12, d = e - s * 12;
                    int q = s0 + s;
                    int b = q >> 7, i = q & 127;
                    int pr = d / 6, rm = d - pr * 6;
                    int pc = rm / 3, ch = rm - pc * 3;
                    sXH[s * K + d] =
                        src[((b * 256 + (2 * jin + pr)) * 256 + (2 * i + pc)) * 3 + ch];
                }
            } else {
                const int iin = dir ? (SJ - 2 - t) : (t + 1);
#pragma unroll
                for (int r = 0; r < 4; r++) {
                    int idx = tid + NTHR * r;
                    int s = idx >> 5, f4 = idx & 31;
                    int q = s0 + s;
                    int b = q >> 7, j = q & 127;
                    float4 v4 = *(const float4*)
                        &src[((size_t)((b * 128 + j) * 128 + iin)) * 128 + f4 * 4];
                    *(float4*)&sXH[s * K + f4 * 4] = v4;
                }
            }
        }
    }
}

extern "C" void kernel_launch(void* const* d_in, const int* in_sizes, int n_in,
                              void* d_out, int out_size)
{
    const float* inputs = (const float*)d_in[0];
    const float* W_ud = (const float*)d_in[1];
    const float* U_ud = (const float*)d_in[2];
    const float* b_ud = (const float*)d_in[3];
    const float* W_du = (const float*)d_in[4];
    const float* U_du = (const float*)d_in[5];
    const float* b_du = (const float*)d_in[6];
    const float* W_lr = (const float*)d_in[7];
    const float* U_lr = (const float*)d_in[8];
    const float* b_lr = (const float*)d_in[9];
    const float* W_rl = (const float*)d_in[10];
    const float* U_rl = (const float*)d_in[11];
    const float* b_rl = (const float*)d_in[12];

    float* vbuf = nullptr;
    cudaGetSymbolAddress((void**)&vbuf, g_v);

    constexpr int K1 = 12 + HIDN;    // 76
    constexpr int K2 = 128 + HIDN;   // 192
    size_t smem1 = (size_t)(K1 * NGC + NSEQ * K1 + NGC) * sizeof(float);  //  88,576 B
    size_t smem2 = (size_t)(K2 * NGC + NSEQ * K2 + NGC) * sizeof(float);  // 222,208 B

    cudaFuncSetAttribute(renet_pass<12>,  cudaFuncAttributeMaxDynamicSharedMemorySize, (int)smem1);
    cudaFuncSetAttribute(renet_pass<128>, cudaFuncAttributeMaxDynamicSharedMemorySize, (int)smem2);

    renet_pass<12><<<128, NTHR, smem1>>>(W_ud, U_ud, b_ud, W_du, U_du, b_du,
                                         inputs, vbuf);
    renet_pass<128><<<128, NTHR, smem2>>>(W_lr, U_lr, b_lr, W_rl, U_rl, b_rl,
                                          vbuf, (float*)d_out);
}

// round 5
// speedup vs baseline: 1.3999x; 1.0012x over previous
#include <cuda_runtime.h>

// ReNet layer: vertical bidirectional LSTM sweep over 2x2x3 patches, then
// horizontal bidirectional LSTM sweep. Exact fp32 math (fma.rn.f32x2 packed).
//
// R3: hid-half split, no reduction. 256 threads = 4 seq-groups x 2 hid-halves.
// Each warp: full K, 8 seqs x 32 hid (1 hid/lane), gates packed (i,f),(g,o)
// so every warp owns complete gate sets -> no cross-warp partial exchange,
// 2 syncs/step. Weights stored [k][hh*128 + lane*4 + gate] -> conflict-free
// LDS.128.

#define HIDN 64
#define NGC  256      // 4*HID gate columns
#define BN   16
#define SJ   128      // J == I == 128 patches
#define NSEQ 32       // sequences per CTA
#define NTHR 256

typedef unsigned long long ull;

__device__ float g_v[BN * SJ * SJ * 2 * HIDN];   // vertical output [B][J][I][128]

__device__ __forceinline__ ull pack2(float lo, float hi) {
    ull r; asm("mov.b64 %0, {%1, %2};" : "=l"(r) : "f"(lo), "f"(hi)); return r;
}
__device__ __forceinline__ void unpack2(ull v, float& lo, float& hi) {
    asm("mov.b64 {%0, %1}, %2;" : "=f"(lo), "=f"(hi) : "l"(v));
}
__device__ __forceinline__ void ffma2(ull& d, ull a, ull b) {
    asm("fma.rn.f32x2 %0, %1, %2, %0;" : "+l"(d) : "l"(a), "l"(b));
}
__device__ __forceinline__ float sigf(float x)   { return 1.0f / (1.0f + __expf(-x)); }
__device__ __forceinline__ float mytanh(float x) { return 1.0f - 2.0f / (__expf(2.0f * x) + 1.0f); }

template <int DIN>
__global__ void __launch_bounds__(NTHR, 1)
renet_pass(const float* __restrict__ W0, const float* __restrict__ U0, const float* __restrict__ b0,
           const float* __restrict__ W1, const float* __restrict__ U1, const float* __restrict__ b1,
           const float* __restrict__ src, float* __restrict__ dst)
{
    constexpr int K = DIN + HIDN;
    extern __shared__ float sm[];
    float* sWU = sm;                   // [K][NGC]  combined W;U, gate-pair layout
    float* sXH = sm + K * NGC;         // [NSEQ][K] per-seq (x_t ++ h)
    float* sB  = sXH + NSEQ * K;       // [NGC]

    const int dir  = blockIdx.x >> 6;
    const int s0   = (blockIdx.x & 63) * NSEQ;
    const int tid  = threadIdx.x;
    const int lane = tid & 31;
    const int wid  = tid >> 5;
    const int hh   = wid & 1;                 // hid half
    const int sg   = wid >> 1;                // seq group: 8 seqs
    const int hid  = hh * 32 + lane;          // this lane's hidden index

    const float* W  = dir ? W1 : W0;
    const float* U  = dir ? U1 : U0;
    const float* bb = dir ? b1 : b0;

    // weight layout: sWU[k][ (h>>5)*128 + (h&31)*4 + g ] = orig[k][g*64 + h]
    // -> per (warp,k): LDS.128 at lane*16B, conflict-free; float4 = (wi,wf,wg,wo)
    for (int idx = tid; idx < K * NGC; idx += NTHR) {
        int k = idx >> 8, c = idx & 255;
        int g = c >> 6, h = c & 63;
        int pc = (h >> 5) * 128 + (h & 31) * 4 + g;
        float v = (k < DIN) ? W[k * NGC + c] : U[(k - DIN) * NGC + c];
        sWU[k * NGC + pc] = v;
    }
    for (int idx = tid; idx < NGC; idx += NTHR) sB[idx] = bb[idx];
    for (int idx = tid; idx < NSEQ * HIDN; idx += NTHR) {
        int s = idx >> 6, h = idx & 63;
        sXH[s * K + DIN + h] = 0.0f;           // h_0 = 0
    }
    __syncthreads();

    // bias packed per lane: (b_i,b_f) and (b_g,b_o) for this hid
    ull binit[2];
    binit[0] = pack2(sB[0 * HIDN + hid], sB[1 * HIDN + hid]);
    binit[1] = pack2(sB[2 * HIDN + hid], sB[3 * HIDN + hid]);

    float cst[8];                              // c-state: 8 seqs x 1 hid
#pragma unroll
    for (int p = 0; p < 8; p++) cst[p] = 0.0f;

    // ---- stage x_0
    {
        if (DIN == 12) {
            const int jin = dir ? (SJ - 1) : 0;
            for (int e = tid; e < NSEQ * 12; e += NTHR) {
                int s = e / 12, d = e - s * 12;
                int q = s0 + s;
                int b = q >> 7, i = q & 127;
                int pr = d / 6, rm = d - pr * 6;
                int pc = rm / 3, ch = rm - pc * 3;
                sXH[s * K + d] =
                    src[((b * 256 + (2 * jin + pr)) * 256 + (2 * i + pc)) * 3 + ch];
            }
        } else {
            const int iin = dir ? (SJ - 1) : 0;
#pragma unroll
            for (int r = 0; r < 4; r++) {
                int idx = tid + NTHR * r;
                int s = idx >> 5, f4 = idx & 31;
                int q = s0 + s;
                int b = q >> 7, j = q & 127;
                float4 v4 = *(const float4*)
                    &src[((size_t)((b * 128 + j) * 128 + iin)) * 128 + f4 * 4];
                *(float4*)&sXH[s * K + f4 * 4] = v4;
            }
        }
    }

    for (int t = 0; t < SJ; t++) {
        __syncthreads();                       // A: x_t staged, h_{t-1} visible

        // ---- Z[s][hid gates] = bias + (x ++ h) @ (W ;; U), full K per warp
        ull acc[8][2];
#pragma unroll
        for (int m = 0; m < 8; m++) {
            acc[m][0] = binit[0];
            acc[m][1] = binit[1];
        }

        const float* xbase = sXH + (sg * 8) * K;
        const float* wbase = sWU + hh * 128 + lane * 4;
#pragma unroll 2
        for (int k = 0; k < K; k += 4) {
            float4 xq[8];
#pragma unroll
            for (int m = 0; m < 8; m++)
                xq[m] = *(const float4*)&xbase[m * K + k];
            const float* xf = (const float*)xq;
#pragma unroll
            for (int kk = 0; kk < 4; kk++) {
                ulonglong2 w2 = *(const ulonglong2*)(wbase + (k + kk) * NGC);
#pragma unroll
                for (int m = 0; m < 8; m++) {
                    float a = xf[m * 4 + kk];
                    ull a2 = pack2(a, a);
                    ffma2(acc[m][0], a2, w2.x);   // (zi, zf)
                    ffma2(acc[m][1], a2, w2.y);   // (zg, zo)
                }
            }
        }
        __syncthreads();                       // B: all sXH reads done

        // ---- gates, state update, h write-back + global store
#pragma unroll
        for (int m = 0; m < 8; m++) {
            float zi, zf, zg, zo;
            unpack2(acc[m][0], zi, zf);
            unpack2(acc[m][1], zg, zo);
            float c = sigf(zf) * cst[m] + sigf(zi) * mytanh(zg);
            cst[m] = c;
            float hv = sigf(zo) * mytanh(c);

            int s = sg * 8 + m;
            sXH[s * K + DIN + hid] = hv;

            int q = s0 + s;
            int b = q >> 7, w = q & 127;
            int row = (DIN == 12) ? t : w;
            int col = (DIN == 12) ? w : t;
            dst[((size_t)((b * 128 + row) * 128 + col)) * 128 + dir * 64 + hid] = hv;
        }

        // ---- stage x_{t+1} (disjoint smem region; reads of x_t finished)
        if (t + 1 < SJ) {
            if (DIN == 12) {
                const int jin = dir ? (SJ - 2 - t) : (t + 1);
                for (int e = tid; e < NSEQ * 12; e += NTHR) {
                    int s = e / 12, d = e - s * 12;
                    int q = s0 + s;
                    int b = q >> 7, i = q & 127;
                    int pr = d / 6, rm = d - pr * 6;
                    int pc = rm / 3, ch = rm - pc * 3;
                    sXH[s * K + d] =
                        src[((b * 256 + (2 * jin + pr)) * 256 + (2 * i + pc)) * 3 + ch];
                }
            } else {
                const int iin = dir ? (SJ - 2 - t) : (t + 1);
#pragma unroll
                for (int r = 0; r < 4; r++) {
                    int idx = tid + NTHR * r;
                    int s = idx >> 5, f4 = idx & 31;
                    int q = s0 + s;
                    int b = q >> 7, j = q & 127;
                    float4 v4 = *(const float4*)
                        &src[((size_t)((b * 128 + j) * 128 + iin)) * 128 + f4 * 4];
                    *(float4*)&sXH[s * K + f4 * 4] = v4;
                }
            }
        }
    }
}

extern "C" void kernel_launch(void* const* d_in, const int* in_sizes, int n_in,
                              void* d_out, int out_size)
{
    const float* inputs = (const float*)d_in[0];
    const float* W_ud = (const float*)d_in[1];
    const float* U_ud = (const float*)d_in[2];
    const float* b_ud = (const float*)d_in[3];
    const float* W_du = (const float*)d_in[4];
    const float* U_du = (const float*)d_in[5];
    const float* b_du = (const float*)d_in[6];
    const float* W_lr = (const float*)d_in[7];
    const float* U_lr = (const float*)d_in[8];
    const float* b_lr = (const float*)d_in[9];
    const float* W_rl = (const float*)d_in[10];
    const float* U_rl = (const float*)d_in[11];
    const float* b_rl = (const float*)d_in[12];

    float* vbuf = nullptr;
    cudaGetSymbolAddress((void**)&vbuf, g_v);

    constexpr int K1 = 12 + HIDN;    // 76
    constexpr int K2 = 128 + HIDN;   // 192
    size_t smem1 = (size_t)(K1 * NGC + NSEQ * K1 + NGC) * sizeof(float);  //  88,576 B
    size_t smem2 = (size_t)(K2 * NGC + NSEQ * K2 + NGC) * sizeof(float);  // 222,208 B

    cudaFuncSetAttribute(renet_pass<12>,  cudaFuncAttributeMaxDynamicSharedMemorySize, (int)smem1);
    cudaFuncSetAttribute(renet_pass<128>, cudaFuncAttributeMaxDynamicSharedMemorySize, (int)smem2);

    renet_pass<12><<<128, NTHR, smem1>>>(W_ud, U_ud, b_ud, W_du, U_du, b_du,
                                         inputs, vbuf);
    renet_pass<128><<<128, NTHR, smem2>>>(W_lr, U_lr, b_lr, W_rl, U_rl, b_rl,
                                          vbuf, (float*)d_out);
}

// round 6
// speedup vs baseline: 1.5009x; 1.0721x over previous
#include <cuda_runtime.h>

// ReNet layer: vertical bidirectional LSTM sweep over 2x2x3 patches, then
// horizontal bidirectional LSTM sweep. Exact fp32 math (fma.rn.f32x2 packed).
//
// R5: pair-decoupled pipelines. 256 threads = 4 independent pairs; each pair
// (2 warps, 64 threads) owns 8 sequences end-to-end: stages its own x, runs
// the hid-half-split GEMM (1 hid/lane/warp, gates packed (i,f),(g,o)), and
// syncs only within the pair via named barriers -> no full-CTA convoy.
// GEMM inner loop is explicitly register-double-buffered (4-k half chunks).

#define HIDN 64
#define NGC  256      // 4*HID gate columns
#define BN   16
#define SJ   128      // J == I == 128 patches
#define NSEQ 32       // sequences per CTA
#define NTHR 256

typedef unsigned long long ull;

__device__ float g_v[BN * SJ * SJ * 2 * HIDN];   // vertical output [B][J][I][128]

__device__ __forceinline__ ull pack2(float lo, float hi) {
    ull r; asm("mov.b64 %0, {%1, %2};" : "=l"(r) : "f"(lo), "f"(hi)); return r;
}
__device__ __forceinline__ void unpack2(ull v, float& lo, float& hi) {
    asm("mov.b64 {%0, %1}, %2;" : "=f"(lo), "=f"(hi) : "l"(v));
}
__device__ __forceinline__ void ffma2(ull& d, ull a, ull b) {
    asm("fma.rn.f32x2 %0, %1, %2, %0;" : "+l"(d) : "l"(a), "l"(b));
}
__device__ __forceinline__ float sigf(float x)   { return 1.0f / (1.0f + __expf(-x)); }
__device__ __forceinline__ float mytanh(float x) { return 1.0f - 2.0f / (__expf(2.0f * x) + 1.0f); }
__device__ __forceinline__ void bar_pair(int sg) {
    asm volatile("bar.sync %0, 64;" :: "r"(sg + 1) : "memory");
}

template <int DIN>
__global__ void __launch_bounds__(NTHR, 1)
renet_pass(const float* __restrict__ W0, const float* __restrict__ U0, const float* __restrict__ b0,
           const float* __restrict__ W1, const float* __restrict__ U1, const float* __restrict__ b1,
           const float* __restrict__ src, float* __restrict__ dst)
{
    constexpr int K  = DIN + HIDN;
    constexpr int KP = (K + 7) & ~7;          // padded to 8 (zero weights / zero x pad)
    extern __shared__ float sm[];
    float* sWU = sm;                   // [KP][NGC]  combined W;U, gate-pair layout
    float* sXH = sm + KP * NGC;        // [NSEQ][KP] per-seq (x_t ++ h ++ pad)
    float* sB  = sXH + NSEQ * KP;      // [NGC]

    const int dir  = blockIdx.x >> 6;
    const int s0   = (blockIdx.x & 63) * NSEQ;
    const int tid  = threadIdx.x;
    const int lane = tid & 31;
    const int wid  = tid >> 5;
    const int hh   = wid & 1;                 // hid half
    const int sg   = wid >> 1;                // pair index: 8 seqs
    const int ptid = tid & 63;                // thread id within pair
    const int hid  = hh * 32 + lane;

    const float* W  = dir ? W1 : W0;
    const float* U  = dir ? U1 : U0;
    const float* bb = dir ? b1 : b0;

    // weight layout: sWU[k][ (h>>5)*128 + (h&31)*4 + g ] = orig[k][g*64 + h]
    for (int idx = tid; idx < KP * NGC; idx += NTHR) {
        int k = idx >> 8, c = idx & 255;
        int g = c >> 6, h = c & 63;
        int pc = (h >> 5) * 128 + (h & 31) * 4 + g;
        float v = (k < DIN) ? W[k * NGC + c]
                 : (k < K)  ? U[(k - DIN) * NGC + c] : 0.0f;
        sWU[k * NGC + pc] = v;
    }
    for (int idx = tid; idx < NGC; idx += NTHR) sB[idx] = bb[idx];
    // zero h region + K-pad region of every sXH row
    for (int idx = tid; idx < NSEQ * (KP - DIN); idx += NTHR) {
        int s = idx / (KP - DIN), o = idx % (KP - DIN);
        sXH[s * KP + DIN + o] = 0.0f;
    }
    __syncthreads();

    ull binit[2];
    binit[0] = pack2(sB[0 * HIDN + hid], sB[1 * HIDN + hid]);
    binit[1] = pack2(sB[2 * HIDN + hid], sB[3 * HIDN + hid]);

    float cst[8];
#pragma unroll
    for (int p = 0; p < 8; p++) cst[p] = 0.0f;

    // ---- pair-local x staging for step t into rows [8sg, 8sg+8)
    auto stage_x = [&](int t) {
        if (DIN == 12) {
            const int jin = dir ? (SJ - 1 - t) : t;
            for (int e = ptid; e < 8 * 12; e += 64) {
                int sl = e / 12, d = e - sl * 12;
                int q = s0 + sg * 8 + sl;
                int b = q >> 7, i = q & 127;
                int pr = d / 6, rm = d - pr * 6;
                int pc = rm / 3, ch = rm - pc * 3;
                sXH[(sg * 8 + sl) * KP + d] =
                    src[((b * 256 + (2 * jin + pr)) * 256 + (2 * i + pc)) * 3 + ch];
            }
        } else {
            const int iin = dir ? (SJ - 1 - t) : t;
#pragma unroll
            for (int r = 0; r < 4; r++) {
                int idx = ptid + 64 * r;       // 256 = 8 seq * 32 float4
                int sl = idx >> 5, f4 = idx & 31;
                int q = s0 + sg * 8 + sl;
                int b = q >> 7, j = q & 127;
                float4 v4 = *(const float4*)
                    &src[((size_t)((b * 128 + j) * 128 + iin)) * 128 + f4 * 4];
                *(float4*)&sXH[(sg * 8 + sl) * KP + f4 * 4] = v4;
            }
        }
    };

    stage_x(0);

    const float* xbase = sXH + (sg * 8) * KP;
    const float* wbase = sWU + hh * 128 + lane * 4;

    for (int t = 0; t < SJ; t++) {
        bar_pair(sg);                          // A: x_t staged, h_{t-1} visible

        ull acc[8][2];
#pragma unroll
        for (int m = 0; m < 8; m++) {
            acc[m][0] = binit[0];
            acc[m][1] = binit[1];
        }

        float4 xA[8], xB[8];
        ulonglong2 wA[4], wB[4];

        auto loadx = [&](float4* xq, int k) {
#pragma unroll
            for (int m = 0; m < 8; m++) xq[m] = *(const float4*)&xbase[m * KP + k];
        };
        auto loadw = [&](ulonglong2* wq, int k) {
#pragma unroll
            for (int kk = 0; kk < 4; kk++)
                wq[kk] = *(const ulonglong2*)(wbase + (k + kk) * NGC);
        };
        auto chunk = [&](const float4* xq, const ulonglong2* wq) {
#pragma unroll
            for (int kk = 0; kk < 4; kk++) {
#pragma unroll
                for (int m = 0; m < 8; m++) {
                    float a = ((const float*)&xq[m])[kk];
                    ull a2 = pack2(a, a);
                    ffma2(acc[m][0], a2, wq[kk].x);   // (zi, zf)
                    ffma2(acc[m][1], a2, wq[kk].y);   // (zg, zo)
                }
            }
        };

        loadx(xA, 0); loadw(wA, 0);
#pragma unroll 1
        for (int k = 0; k < KP; k += 8) {
            loadx(xB, k + 4); loadw(wB, k + 4);
            chunk(xA, wA);
            if (k + 8 < KP) { loadx(xA, k + 8); loadw(wA, k + 8); }
            chunk(xB, wB);
        }

        bar_pair(sg);                          // B: pair's reads of sXH done

        // ---- gates, state update, h write-back + global store
#pragma unroll
        for (int m = 0; m < 8; m++) {
            float zi, zf, zg, zo;
            unpack2(acc[m][0], zi, zf);
            unpack2(acc[m][1], zg, zo);
            float c = sigf(zf) * cst[m] + sigf(zi) * mytanh(zg);
            cst[m] = c;
            float hv = sigf(zo) * mytanh(c);

            int s = sg * 8 + m;
            sXH[s * KP + DIN + hid] = hv;

            int q = s0 + s;
            int b = q >> 7, w = q & 127;
            int row = (DIN == 12) ? t : w;
            int col = (DIN == 12) ? w : t;
            dst[((size_t)((b * 128 + row) * 128 + col)) * 128 + dir * 64 + hid] = hv;
        }

        if (t + 1 < SJ) stage_x(t + 1);        // x region disjoint from h region
    }
}

extern "C" void kernel_launch(void* const* d_in, const int* in_sizes, int n_in,
                              void* d_out, int out_size)
{
    const float* inputs = (const float*)d_in[0];
    const float* W_ud = (const float*)d_in[1];
    const float* U_ud = (const float*)d_in[2];
    const float* b_ud = (const float*)d_in[3];
    const float* W_du = (const float*)d_in[4];
    const float* U_du = (const float*)d_in[5];
    const float* b_du = (const float*)d_in[6];
    const float* W_lr = (const float*)d_in[7];
    const float* U_lr = (const float*)d_in[8];
    const float* b_lr = (const float*)d_in[9];
    const float* W_rl = (const float*)d_in[10];
    const float* U_rl = (const float*)d_in[11];
    const float* b_rl = (const float*)d_in[12];

    float* vbuf = nullptr;
    cudaGetSymbolAddress((void**)&vbuf, g_v);

    constexpr int KP1 = 80;    // (12+64) padded to 8
    constexpr int KP2 = 192;   // 128+64
    size_t smem1 = (size_t)(KP1 * NGC + NSEQ * KP1 + NGC) * sizeof(float);  //  93,184 B
    size_t smem2 = (size_t)(KP2 * NGC + NSEQ * KP2 + NGC) * sizeof(float);  // 222,208 B

    cudaFuncSetAttribute(renet_pass<12>,  cudaFuncAttributeMaxDynamicSharedMemorySize, (int)smem1);
    cudaFuncSetAttribute(renet_pass<128>, cudaFuncAttributeMaxDynamicSharedMemorySize, (int)smem2);

    renet_pass<12><<<128, NTHR, smem1>>>(W_ud, U_ud, b_ud, W_du, U_du, b_du,
                                         inputs, vbuf);
    renet_pass<128><<<128, NTHR, smem2>>>(W_lr, U_lr, b_lr, W_rl, U_rl, b_rl,
                                          vbuf, (float*)d_out);
}